// round 2
// baseline (speedup 1.0000x reference)
#include <cuda_runtime.h>

// Problem constants
#define B_ROWS   2048
#define NFEAT    128
#define NCOLS    256        // [V | T] columns
#define K_TOTAL  50000
#define U_DIM    10000
#define X_DIM    20000
#define KCHUNK   2560       // k-split chunk (multiple of 8; remainders 2320/2080 also mult of 8)

// Scratch (device globals — no allocation allowed)
__device__ float g_accS[B_ROWS * NCOLS];   // [u,x_prev] @ [V|T]
__device__ float g_accP[B_ROWS * NCOLS];   // x_pos @ [V|T]
__device__ float g_accN[B_ROWS * NCOLS];   // x_neg @ [V|T]
__device__ float g_scal[3 * B_ROWS * 8];   // per-row scalar dots: [dst][row][vv,tt,vt,W,sum,pad..]
__device__ float g_gram[K_TOTAL * 4];      // per-K-row: vv, tt, vt, 0

// ---------------------------------------------------------------------------
__global__ void zero_kernel() {
    int idx = blockIdx.x * blockDim.x + threadIdx.x;
    if (idx < B_ROWS * NCOLS) {
        g_accS[idx] = 0.f;
        g_accP[idx] = 0.f;
        g_accN[idx] = 0.f;
    }
    if (idx < 3 * B_ROWS * 8) g_scal[idx] = 0.f;
}

// ---------------------------------------------------------------------------
// Per-K-row Gram diagonals: vv = sum_f V^2, tt = sum_f T^2, vt = sum_f V*T
__global__ void gram_kernel(const float* __restrict__ V, const float* __restrict__ T) {
    int warp = threadIdx.x >> 5, lane = threadIdx.x & 31;
    int k = blockIdx.x * 8 + warp;
    if (k >= K_TOTAL) return;
    float4 v = reinterpret_cast<const float4*>(V + (size_t)k * NFEAT)[lane];
    float4 t = reinterpret_cast<const float4*>(T + (size_t)k * NFEAT)[lane];
    float vv = v.x * v.x + v.y * v.y + v.z * v.z + v.w * v.w;
    float tt = t.x * t.x + t.y * t.y + t.z * t.z + t.w * t.w;
    float vt = v.x * t.x + v.y * t.y + v.z * t.z + v.w * t.w;
#pragma unroll
    for (int o = 16; o; o >>= 1) {
        vv += __shfl_down_sync(0xffffffffu, vv, o);
        tt += __shfl_down_sync(0xffffffffu, tt, o);
        vt += __shfl_down_sync(0xffffffffu, vt, o);
    }
    if (lane == 0) {
        g_gram[k * 4 + 0] = vv;
        g_gram[k * 4 + 1] = tt;
        g_gram[k * 4 + 2] = vt;
        g_gram[k * 4 + 3] = 0.f;
    }
}

// ---------------------------------------------------------------------------
// Split-K SGEMM with atomic reduction.
// grid = (8 k-chunks, 16 M-tiles, 8 z) ; z = seg*2 + mat
//   seg: 0=u->accS, 1=x_prev->accS, 2=x_pos->accP, 3=x_neg->accN
//   mat: 0=V (cols 0..127), 1=T (cols 128..255)
// B (V/T) rows are indexed by the GLOBAL K position: segOff + local k.
__global__ void __launch_bounds__(256, 2) gemm_kernel(
    const float* __restrict__ u, const float* __restrict__ xprev,
    const float* __restrict__ xpos, const float* __restrict__ xneg,
    const float* __restrict__ V, const float* __restrict__ T)
{
    int z = blockIdx.z;
    int seg = z >> 1, mat = z & 1;

    const float* A;
    int lda, kLen, segOff;
    float* acc;
    if (seg == 0)      { A = u;     lda = U_DIM; kLen = U_DIM; segOff = 0;             acc = g_accS; }
    else if (seg == 1) { A = xprev; lda = X_DIM; kLen = X_DIM; segOff = U_DIM;         acc = g_accS; }
    else if (seg == 2) { A = xpos;  lda = X_DIM; kLen = X_DIM; segOff = U_DIM + X_DIM; acc = g_accP; }
    else               { A = xneg;  lda = X_DIM; kLen = X_DIM; segOff = U_DIM + X_DIM; acc = g_accN; }
    const float* Bm = mat ? T : V;
    int colOff = mat * NFEAT;

    int kStart = blockIdx.x * KCHUNK;
    if (kStart >= kLen) return;
    int kEnd = min(kStart + KCHUNK, kLen);
    int m0 = blockIdx.y * 128;

    __shared__ float As[2][8][128];
    __shared__ float Bs[2][8][128];

    int tid = threadIdx.x;
    int tx = tid & 15, ty = tid >> 4;        // 16x16 thread grid, 8x8 per thread
    int arow = tid >> 1, acol = (tid & 1) * 4;
    int brow = tid >> 5, bcol = (tid & 31) * 4;

    const float* aPtr = A + (size_t)(m0 + arow) * lda;
    const float* bPtr = Bm + (size_t)segOff * NFEAT;   // global K offset for V/T rows

    float r[8][8];
#pragma unroll
    for (int i = 0; i < 8; i++)
#pragma unroll
        for (int j = 0; j < 8; j++) r[i][j] = 0.f;

    // prime buffer 0
    float4 aReg = *reinterpret_cast<const float4*>(aPtr + kStart + acol);
    float4 bReg = *reinterpret_cast<const float4*>(bPtr + (size_t)(kStart + brow) * NFEAT + bcol);
    As[0][acol + 0][arow] = aReg.x;
    As[0][acol + 1][arow] = aReg.y;
    As[0][acol + 2][arow] = aReg.z;
    As[0][acol + 3][arow] = aReg.w;
    *reinterpret_cast<float4*>(&Bs[0][brow][bcol]) = bReg;
    __syncthreads();

    int cur = 0;
    for (int k = kStart; k < kEnd; k += 8) {
        bool hasNext = (k + 8) < kEnd;
        if (hasNext) {
            aReg = *reinterpret_cast<const float4*>(aPtr + (k + 8) + acol);
            bReg = *reinterpret_cast<const float4*>(bPtr + (size_t)(k + 8 + brow) * NFEAT + bcol);
        }
#pragma unroll
        for (int kk = 0; kk < 8; kk++) {
            float a[8], b[8];
            *reinterpret_cast<float4*>(a)     = *reinterpret_cast<float4*>(&As[cur][kk][ty * 8]);
            *reinterpret_cast<float4*>(a + 4) = *reinterpret_cast<float4*>(&As[cur][kk][ty * 8 + 4]);
            *reinterpret_cast<float4*>(b)     = *reinterpret_cast<float4*>(&Bs[cur][kk][tx * 8]);
            *reinterpret_cast<float4*>(b + 4) = *reinterpret_cast<float4*>(&Bs[cur][kk][tx * 8 + 4]);
#pragma unroll
            for (int i = 0; i < 8; i++)
#pragma unroll
                for (int j = 0; j < 8; j++) r[i][j] += a[i] * b[j];
        }
        if (hasNext) {
            int nb = cur ^ 1;
            As[nb][acol + 0][arow] = aReg.x;
            As[nb][acol + 1][arow] = aReg.y;
            As[nb][acol + 2][arow] = aReg.z;
            As[nb][acol + 3][arow] = aReg.w;
            *reinterpret_cast<float4*>(&Bs[nb][brow][bcol]) = bReg;
            __syncthreads();
            cur = nb;
        }
    }

#pragma unroll
    for (int i = 0; i < 8; i++) {
        float* dst = acc + (size_t)(m0 + ty * 8 + i) * NCOLS + colOff + tx * 8;
#pragma unroll
        for (int j = 0; j < 8; j++) atomicAdd(dst + j, r[i][j]);
    }
}

// ---------------------------------------------------------------------------
// Per-row scalar reductions: z . {vv, tt, vt, W, 1}
// grid = (8 k-chunks, 256 row blocks, 4 segments), block = 256 (8 warps, warp=row)
__global__ void scal_kernel(
    const float* __restrict__ u, const float* __restrict__ xprev,
    const float* __restrict__ xpos, const float* __restrict__ xneg,
    const float* __restrict__ W)
{
    int seg = blockIdx.z;
    const float* A;
    int lda, kLen, segOff, dst;
    if (seg == 0)      { A = u;     lda = U_DIM; kLen = U_DIM; segOff = 0;             dst = 0; }
    else if (seg == 1) { A = xprev; lda = X_DIM; kLen = X_DIM; segOff = U_DIM;         dst = 0; }
    else if (seg == 2) { A = xpos;  lda = X_DIM; kLen = X_DIM; segOff = U_DIM + X_DIM; dst = 1; }
    else               { A = xneg;  lda = X_DIM; kLen = X_DIM; segOff = U_DIM + X_DIM; dst = 2; }

    int warp = threadIdx.x >> 5, lane = threadIdx.x & 31;
    int row = blockIdx.y * 8 + warp;
    int kStart = blockIdx.x * KCHUNK;
    if (kStart >= kLen) return;
    int kEnd = min(kStart + KCHUNK, kLen);

    const float* aRow = A + (size_t)row * lda;
    float s0 = 0.f, s1 = 0.f, s2 = 0.f, s3 = 0.f, s4 = 0.f;
    for (int k = kStart + lane; k < kEnd; k += 32) {
        float zv = aRow[k];
        int kg = segOff + k;
        float4 gr = *reinterpret_cast<const float4*>(g_gram + (size_t)kg * 4);
        s0 += zv * gr.x;     // z . vv
        s1 += zv * gr.y;     // z . tt
        s2 += zv * gr.z;     // z . vt
        s3 += zv * W[kg];    // z . W
        s4 += zv;            // z_sum
    }
#pragma unroll
    for (int o = 16; o; o >>= 1) {
        s0 += __shfl_down_sync(0xffffffffu, s0, o);
        s1 += __shfl_down_sync(0xffffffffu, s1, o);
        s2 += __shfl_down_sync(0xffffffffu, s2, o);
        s3 += __shfl_down_sync(0xffffffffu, s3, o);
        s4 += __shfl_down_sync(0xffffffffu, s4, o);
    }
    if (lane == 0) {
        float* d = g_scal + (size_t)(dst * B_ROWS + row) * 8;
        atomicAdd(d + 0, s0);
        atomicAdd(d + 1, s1);
        atomicAdd(d + 2, s2);
        atomicAdd(d + 3, s3);
        atomicAdd(d + 4, s4);
    }
}

// ---------------------------------------------------------------------------
// Final combine: quadratic form per row, write [pred_pos(2048) | pred_neg(2048)]
__global__ void epilogue_kernel(const float* __restrict__ bias, float* __restrict__ out) {
    int warp = threadIdx.x >> 5, lane = threadIdx.x & 31;
    int row = blockIdx.x * 8 + warp;
    if (row >= B_ROWS) return;

    const float* aS = g_accS + (size_t)row * NCOLS;
    const float* aP = g_accP + (size_t)row * NCOLS;
    const float* aN = g_accN + (size_t)row * NCOLS;

    float t5p = 0.f, t6p = 0.f, dgp = 0.f;
    float t5n = 0.f, t6n = 0.f, dgn = 0.f;
#pragma unroll
    for (int f = lane; f < NFEAT; f += 32) {
        float vs = aS[f],        vp = aP[f],        vn = aN[f];
        float ts = aS[NFEAT + f], tp = aP[NFEAT + f], tn = aN[NFEAT + f];
        float vxp = vs + vp, txp = ts + tp;
        float vxn = vs + vn, txn = ts + tn;
        t5p += vxp * vxp; t6p += txp * vxp; dgp += txp * txp;
        t5n += vxn * vxn; t6n += txn * vxn; dgn += txn * txn;
    }
#pragma unroll
    for (int o = 16; o; o >>= 1) {
        t5p += __shfl_down_sync(0xffffffffu, t5p, o);
        t6p += __shfl_down_sync(0xffffffffu, t6p, o);
        dgp += __shfl_down_sync(0xffffffffu, dgp, o);
        t5n += __shfl_down_sync(0xffffffffu, t5n, o);
        t6n += __shfl_down_sync(0xffffffffu, t6n, o);
        dgn += __shfl_down_sync(0xffffffffu, dgn, o);
    }
    if (lane == 0) {
        const float* sS = g_scal + (size_t)(0 * B_ROWS + row) * 8;
        const float* sP = g_scal + (size_t)(1 * B_ROWS + row) * 8;
        const float* sN = g_scal + (size_t)(2 * B_ROWS + row) * 8;

        float zvvp = sS[0] + sP[0], zttp = sS[1] + sP[1], zvtp = sS[2] + sP[2], zsp = sS[4] + sP[4];
        float zvvn = sS[0] + sN[0], zttn = sS[1] + sN[1], zvtn = sS[2] + sN[2], zsn = sS[4] + sN[4];
        float lin_neg = sS[3] + sN[3] + bias[0];

        // quad = 0.5*(t1 + 2*t2 + t4 - t5 - t6) - 0.5*diag
        //   t1 = zs*zvv ; t2 = zs*ztt ; t4 = 2*zs*zvt ; t5 = 2*sum(vx^2) ; t6 = 2*sum(tx*vx)
        float qp = 0.5f * (zsp * zvvp + 2.f * zsp * zttp + 2.f * zsp * zvtp
                           - 2.f * t5p - 2.f * t6p) - 0.5f * dgp;
        float qn = 0.5f * (zsn * zvvn + 2.f * zsn * zttn + 2.f * zsn * zvtn
                           - 2.f * t5n - 2.f * t6n) - 0.5f * dgn;

        out[row]          = lin_neg + qp;   // pred_pos
        out[B_ROWS + row] = lin_neg + qn;   // pred_neg
    }
}

// ---------------------------------------------------------------------------
extern "C" void kernel_launch(void* const* d_in, const int* in_sizes, int n_in,
                              void* d_out, int out_size) {
    const float* u     = (const float*)d_in[0];
    const float* xprev = (const float*)d_in[1];
    const float* xpos  = (const float*)d_in[2];
    const float* xneg  = (const float*)d_in[3];
    const float* V     = (const float*)d_in[4];
    const float* T     = (const float*)d_in[5];
    const float* W     = (const float*)d_in[6];
    const float* bias  = (const float*)d_in[7];
    float* out = (float*)d_out;

    zero_kernel<<<(B_ROWS * NCOLS + 255) / 256, 256>>>();
    gram_kernel<<<K_TOTAL / 8, 256>>>(V, T);
    gemm_kernel<<<dim3(8, B_ROWS / 128, 8), 256>>>(u, xprev, xpos, xneg, V, T);
    scal_kernel<<<dim3(8, B_ROWS / 8, 4), 256>>>(u, xprev, xpos, xneg, W);
    epilogue_kernel<<<B_ROWS / 8, 256>>>(bias, out);
}

// round 4
// speedup vs baseline: 2.0597x; 2.0597x over previous
#include <cuda_runtime.h>

// ---------------------------------------------------------------------------
// Problem constants
#define B_ROWS   2048
#define NFEAT    128
#define NCOLS    256        // [V | T] columns
#define K_TOTAL  50000
#define KPAD     50048      // padded (multiple of 64), pad zero-filled
#define U_DIM    10000
#define X_DIM    20000
#define KCHUNK   2560       // split-K chunk (multiple of 16)
#define SMEM_DYN 132096     // 2 x 64KB buffers + 1KB align slack

// ---------------------------------------------------------------------------
// Device-global scratch (no allocation allowed)
__device__ unsigned short BT_hi[(size_t)NCOLS * KPAD];   // [V|T]^T bf16 hi plane, K-major
__device__ unsigned short BT_lo[(size_t)NCOLS * KPAD];   // bf16 lo plane
__device__ float g_acc[(size_t)3 * B_ROWS * NCOLS];      // [S|P|N][row][col]
__device__ float g_scal[3 * B_ROWS * 8];                 // [dst][row][vv,tt,vt,W,sum,...]
__device__ float g_vv[K_TOTAL], g_tt[K_TOTAL], g_vt[K_TOTAL];

// ---------------------------------------------------------------------------
__device__ __forceinline__ unsigned smem_u32(const void* p) {
    unsigned r;
    asm("{ .reg .u64 t; cvta.to.shared.u64 t, %1; cvt.u32.u64 %0, t; }" : "=r"(r) : "l"(p));
    return r;
}
// bf16 truncation split: hi = top16(f), lo = top16(f - hi) (packed pairwise)
__device__ __forceinline__ void split2(float f0, float f1, unsigned& h, unsigned& l) {
    unsigned b0 = __float_as_uint(f0), b1 = __float_as_uint(f1);
    h = __byte_perm(b0, b1, 0x7632);
    float l0 = f0 - __uint_as_float(b0 & 0xFFFF0000u);
    float l1 = f1 - __uint_as_float(b1 & 0xFFFF0000u);
    l = __byte_perm(__float_as_uint(l0), __float_as_uint(l1), 0x7632);
}
__device__ __forceinline__ void ldsm4(unsigned* r, unsigned a) {
    asm volatile("ldmatrix.sync.aligned.m8n8.x4.shared.b16 {%0,%1,%2,%3}, [%4];"
                 : "=r"(r[0]), "=r"(r[1]), "=r"(r[2]), "=r"(r[3]) : "r"(a));
}
__device__ __forceinline__ void mma16816(float* c, const unsigned* a, const unsigned* b) {
    asm volatile("mma.sync.aligned.m16n8k16.row.col.f32.bf16.bf16.f32 "
                 "{%0,%1,%2,%3}, {%4,%5,%6,%7}, {%8,%9}, {%0,%1,%2,%3};"
                 : "+f"(c[0]), "+f"(c[1]), "+f"(c[2]), "+f"(c[3])
                 : "r"(a[0]), "r"(a[1]), "r"(a[2]), "r"(a[3]), "r"(b[0]), "r"(b[1]));
}

// ---------------------------------------------------------------------------
__global__ void zero_kernel() {
    size_t idx = (size_t)blockIdx.x * blockDim.x + threadIdx.x;
    size_t n = (size_t)3 * B_ROWS * NCOLS;
    for (size_t i = idx; i < n; i += (size_t)gridDim.x * blockDim.x) g_acc[i] = 0.f;
    if (idx < 3 * B_ROWS * 8) g_scal[idx] = 0.f;
}

// ---------------------------------------------------------------------------
// Gram diagonals (planar): vv = sum_f V^2, tt = sum_f T^2, vt = sum_f V*T
__global__ void gram_kernel(const float* __restrict__ V, const float* __restrict__ T) {
    int warp = threadIdx.x >> 5, lane = threadIdx.x & 31;
    int k = blockIdx.x * 8 + warp;
    if (k >= K_TOTAL) return;
    float4 v = reinterpret_cast<const float4*>(V + (size_t)k * NFEAT)[lane];
    float4 t = reinterpret_cast<const float4*>(T + (size_t)k * NFEAT)[lane];
    float vv = v.x*v.x + v.y*v.y + v.z*v.z + v.w*v.w;
    float tt = t.x*t.x + t.y*t.y + t.z*t.z + t.w*t.w;
    float vt = v.x*t.x + v.y*t.y + v.z*t.z + v.w*t.w;
#pragma unroll
    for (int o = 16; o; o >>= 1) {
        vv += __shfl_down_sync(0xffffffffu, vv, o);
        tt += __shfl_down_sync(0xffffffffu, tt, o);
        vt += __shfl_down_sync(0xffffffffu, vt, o);
    }
    if (lane == 0) { g_vv[k] = vv; g_tt[k] = tt; g_vt[k] = vt; }
}

// ---------------------------------------------------------------------------
// Transpose V/T into K-major bf16 hi/lo planes [256 x KPAD]; pad zero-filled.
// grid = (KPAD/64 = 782, 2: V/T), block = 256
__global__ void prep_vt(const float* __restrict__ V, const float* __restrict__ T) {
    __shared__ float tile[64][129];
    const float* S = blockIdx.y ? T : V;
    int nBase = blockIdx.y ? NFEAT : 0;
    int k0 = blockIdx.x * 64;
    int tid = threadIdx.x;
#pragma unroll
    for (int t = 0; t < 8; t++) {
        int idx = tid + t * 256;            // 2048 float4 = 64 rows x 32 f4
        int r = idx >> 5, n4 = idx & 31;
        float4 v = make_float4(0.f, 0.f, 0.f, 0.f);
        if (k0 + r < K_TOTAL)
            v = *reinterpret_cast<const float4*>(S + (size_t)(k0 + r) * NFEAT + n4 * 4);
        tile[r][n4*4+0] = v.x; tile[r][n4*4+1] = v.y;
        tile[r][n4*4+2] = v.z; tile[r][n4*4+3] = v.w;
    }
    __syncthreads();
#pragma unroll
    for (int t = 0; t < 4; t++) {
        int idx = tid + t * 256;            // 1024 tasks = 128 n x 8 k-groups
        int n = idx >> 3, rq = idx & 7;
        int kk = k0 + rq * 8;
        unsigned hw[4], lw[4];
#pragma unroll
        for (int j = 0; j < 4; j++)
            split2(tile[rq*8 + 2*j][n], tile[rq*8 + 2*j + 1][n], hw[j], lw[j]);
        size_t off = (size_t)(nBase + n) * KPAD + kk;
        *reinterpret_cast<uint4*>(BT_hi + off) = make_uint4(hw[0], hw[1], hw[2], hw[3]);
        *reinterpret_cast<uint4*>(BT_lo + off) = make_uint4(lw[0], lw[1], lw[2], lw[3]);
    }
}

// ---------------------------------------------------------------------------
// bf16 mma.sync split-K GEMM with hi/lo 3-product split.
// grid = (28 kchunks, 16 mtiles, 2 ntiles), block = 256 (8 warps, 4m x 2n).
// kc<4: u; <12: x_prev; <20: x_pos; else x_neg.
// n-tile 0 CTAs additionally accumulate z.{vv,tt,vt,W,1} from the A stream.
__global__ void __launch_bounds__(256, 1) gemm_kernel(
    const float* __restrict__ u, const float* __restrict__ xprev,
    const float* __restrict__ xpos, const float* __restrict__ xneg,
    const float* __restrict__ W)
{
    extern __shared__ char dyn[];
    unsigned sraw = smem_u32(dyn);
    unsigned sb = (sraw + 1023u) & ~1023u;
    // buffer layout (per 64KB buf): A_hi @0, A_lo @16384, B_hi @32768, B_lo @49152

    const int tid = threadIdx.x;
    const int lane = tid & 31, warp = tid >> 5;
    const int wr = warp >> 1, wc = warp & 1;    // warp grid 4(m) x 2(n)

    int kc = blockIdx.x;
    const float* A; int lda, kLen, segOff, accIdx, kcL;
    if (kc < 4)       { A = u;     lda = U_DIM; kLen = U_DIM; segOff = 0;             accIdx = 0; kcL = kc; }
    else if (kc < 12) { A = xprev; lda = X_DIM; kLen = X_DIM; segOff = U_DIM;         accIdx = 0; kcL = kc - 4; }
    else if (kc < 20) { A = xpos;  lda = X_DIM; kLen = X_DIM; segOff = U_DIM + X_DIM; accIdx = 1; kcL = kc - 12; }
    else              { A = xneg;  lda = X_DIM; kLen = X_DIM; segOff = U_DIM + X_DIM; accIdx = 2; kcL = kc - 20; }
    const int m0 = blockIdx.y * 128;
    const int nt0 = blockIdx.z;
    const int kStart = kcL * KCHUNK;
    const int kLenC = min(KCHUNK, kLen - kStart);
    const int nsteps = (kLenC + 63) >> 6;
    const bool doScal = (nt0 == 0);

    // ---- producer mapping ----
    const int rowL = tid >> 1;                  // A row within tile (2 threads/row)
    const int kL0 = (tid & 1) * 32;             // k offset within 64-step
    const float* aPtr = A + (size_t)(m0 + rowL) * lda + kStart + kL0;
    const int gBase = segOff + kStart + kL0;

    unsigned bDst[8]; const unsigned short* bSrc[8];
#pragma unroll
    for (int tt = 0; tt < 8; tt++) {
        int idx = tid + tt * 256;               // 2048: plane(2) x n(128) x kq(8)
        int plane = idx >> 10;
        int rn = (idx >> 3) & 127;
        int kq = idx & 7;
        const unsigned short* base = plane ? BT_lo : BT_hi;
        bSrc[tt] = base + (size_t)(nt0 * 128 + rn) * KPAD + (segOff + kStart) + kq * 8;
        unsigned off = rn * 128 + kq * 16;
        bDst[tt] = (plane ? 49152u : 32768u) + (off ^ ((off >> 3) & 0x70));
    }
    unsigned aDst[8];
#pragma unroll
    for (int j = 0; j < 8; j++) {
        unsigned off = rowL * 128 + (kL0 + j * 4) * 2;
        aDst[j] = (off ^ ((off >> 3) & 0x70));
    }
    // ldmatrix per-lane byte offsets (pre-swizzle)
    unsigned aLd[2], bLd[4];
#pragma unroll
    for (int mi = 0; mi < 2; mi++)
        aLd[mi] = (unsigned)((wr*32 + mi*16 + (lane & 15)) * 128 + (lane >> 4) * 16);
#pragma unroll
    for (int nj = 0; nj < 4; nj++)
        bLd[nj] = (unsigned)((wc*64 + nj*16 + ((lane >> 4) << 3) + (lane & 7)) * 128
                             + ((lane >> 3) & 1) * 16);

    float c[2][8][4];
#pragma unroll
    for (int i = 0; i < 2; i++)
#pragma unroll
        for (int j = 0; j < 8; j++)
#pragma unroll
            for (int q = 0; q < 4; q++) c[i][j][q] = 0.f;

    float s0 = 0.f, s1 = 0.f, s2 = 0.f, s3 = 0.f, s4 = 0.f;
    float4 av[8];

#define PREFETCH_A(st) do {                                                     \
    int kst_ = (st) * 64;                                                       \
    _Pragma("unroll")                                                           \
    for (int j = 0; j < 8; j++) {                                               \
        if (kst_ + kL0 + j * 4 < kLenC)                                         \
            av[j] = *reinterpret_cast<const float4*>(aPtr + kst_ + j * 4);      \
        else av[j] = make_float4(0.f, 0.f, 0.f, 0.f);                           \
    }                                                                           \
} while (0)

#define ISSUE_B(st, bufAdr) do {                                                \
    int boff_ = (st) * 64;                                                      \
    _Pragma("unroll")                                                           \
    for (int tt = 0; tt < 8; tt++) {                                            \
        unsigned d_ = (bufAdr) + bDst[tt];                                      \
        const void* s_ = (const void*)(bSrc[tt] + boff_);                       \
        asm volatile("cp.async.cg.shared.global [%0], [%1], 16;"                \
                     :: "r"(d_), "l"(s_) : "memory");                           \
    }                                                                           \
} while (0)

#define STORE_A(bufAdr, st) do {                                                \
    int kst_ = (st) * 64;                                                       \
    _Pragma("unroll")                                                           \
    for (int j = 0; j < 8; j++) {                                               \
        unsigned h01, l01, h23, l23;                                            \
        split2(av[j].x, av[j].y, h01, l01);                                     \
        split2(av[j].z, av[j].w, h23, l23);                                     \
        asm volatile("st.shared.v2.u32 [%0], {%1,%2};"                          \
                     :: "r"((bufAdr) + aDst[j]), "r"(h01), "r"(h23) : "memory");\
        asm volatile("st.shared.v2.u32 [%0], {%1,%2};"                          \
                     :: "r"((bufAdr) + 16384u + aDst[j]), "r"(l01), "r"(l23) : "memory"); \
    }                                                                           \
    if (doScal) {                                                               \
        _Pragma("unroll")                                                       \
        for (int j = 0; j < 8; j++) {                                           \
            if (kst_ + kL0 + j * 4 < kLenC) {                                   \
                int gg_ = gBase + kst_ + j * 4;                                 \
                float4 v4 = *reinterpret_cast<const float4*>(g_vv + gg_);       \
                float4 t4 = *reinterpret_cast<const float4*>(g_tt + gg_);       \
                float4 x4 = *reinterpret_cast<const float4*>(g_vt + gg_);       \
                float4 w4 = *reinterpret_cast<const float4*>(W + gg_);          \
                s0 += av[j].x*v4.x + av[j].y*v4.y + av[j].z*v4.z + av[j].w*v4.w;\
                s1 += av[j].x*t4.x + av[j].y*t4.y + av[j].z*t4.z + av[j].w*t4.w;\
                s2 += av[j].x*x4.x + av[j].y*x4.y + av[j].z*x4.z + av[j].w*x4.w;\
                s3 += av[j].x*w4.x + av[j].y*w4.y + av[j].z*w4.z + av[j].w*w4.w;\
                s4 += av[j].x + av[j].y + av[j].z + av[j].w;                    \
            }                                                                   \
        }                                                                       \
    }                                                                           \
} while (0)

#define DO_MMA(bufAdr) do {                                                     \
    unsigned Ah_ = (bufAdr), Al_ = (bufAdr) + 16384u;                           \
    unsigned Bh_ = (bufAdr) + 32768u, Bl_ = (bufAdr) + 49152u;                  \
    _Pragma("unroll")                                                           \
    for (int kk = 0; kk < 4; kk++) {                                            \
        unsigned ah[2][4], al[2][4], bh[4][4], bl[4][4];                        \
        _Pragma("unroll")                                                       \
        for (int mi = 0; mi < 2; mi++) {                                        \
            unsigned o_ = aLd[mi] + kk * 32, sw_ = o_ ^ ((o_ >> 3) & 0x70);     \
            ldsm4(ah[mi], Ah_ + sw_); ldsm4(al[mi], Al_ + sw_);                 \
        }                                                                       \
        _Pragma("unroll")                                                       \
        for (int nj = 0; nj < 4; nj++) {                                        \
            unsigned o_ = bLd[nj] + kk * 32, sw_ = o_ ^ ((o_ >> 3) & 0x70);     \
            ldsm4(bh[nj], Bh_ + sw_); ldsm4(bl[nj], Bl_ + sw_);                 \
        }                                                                       \
        _Pragma("unroll")                                                       \
        for (int mi = 0; mi < 2; mi++)                                          \
        _Pragma("unroll")                                                       \
        for (int nj = 0; nj < 4; nj++)                                          \
        _Pragma("unroll")                                                       \
        for (int h = 0; h < 2; h++) {                                           \
            float* cc = c[mi][nj * 2 + h];                                      \
            mma16816(cc, ah[mi], &bh[nj][h * 2]);                               \
            mma16816(cc, ah[mi], &bl[nj][h * 2]);                               \
            mma16816(cc, al[mi], &bh[nj][h * 2]);                               \
        }                                                                       \
    }                                                                           \
} while (0)

    const unsigned buf0 = sb, buf1 = sb + 65536u;

    // prologue: fill buffer 0 for step 0
    PREFETCH_A(0);
    ISSUE_B(0, buf0);
    asm volatile("cp.async.commit_group;" ::: "memory");
    STORE_A(buf0, 0);
    asm volatile("cp.async.wait_group 0;" ::: "memory");
    __syncthreads();

    int cur = 0;
    for (int st = 0; st < nsteps; st++) {
        unsigned bc = cur ? buf1 : buf0;
        unsigned bn = cur ? buf0 : buf1;
        bool pf = (st + 1) < nsteps;
        if (pf) { PREFETCH_A(st + 1); ISSUE_B(st + 1, bn); }
        asm volatile("cp.async.commit_group;" ::: "memory");
        DO_MMA(bc);
        if (pf) STORE_A(bn, st + 1);
        asm volatile("cp.async.wait_group 0;" ::: "memory");
        __syncthreads();
        cur ^= 1;
    }

    // epilogue: atomic reduce C tile
    float* accBase = g_acc + (size_t)accIdx * B_ROWS * NCOLS;
    int colBase = nt0 * 128 + wc * 64;
#pragma unroll
    for (int mi = 0; mi < 2; mi++) {
        int r0 = m0 + wr * 32 + mi * 16 + (lane >> 2);
#pragma unroll
        for (int nt = 0; nt < 8; nt++) {
            int c0 = colBase + nt * 8 + (lane & 3) * 2;
            atomicAdd(accBase + (size_t)r0 * NCOLS + c0,           c[mi][nt][0]);
            atomicAdd(accBase + (size_t)r0 * NCOLS + c0 + 1,       c[mi][nt][1]);
            atomicAdd(accBase + (size_t)(r0 + 8) * NCOLS + c0,     c[mi][nt][2]);
            atomicAdd(accBase + (size_t)(r0 + 8) * NCOLS + c0 + 1, c[mi][nt][3]);
        }
    }
    if (doScal) {
        s0 += __shfl_xor_sync(0xffffffffu, s0, 1);
        s1 += __shfl_xor_sync(0xffffffffu, s1, 1);
        s2 += __shfl_xor_sync(0xffffffffu, s2, 1);
        s3 += __shfl_xor_sync(0xffffffffu, s3, 1);
        s4 += __shfl_xor_sync(0xffffffffu, s4, 1);
        if ((tid & 1) == 0) {
            float* d = g_scal + (size_t)(accIdx * B_ROWS + m0 + rowL) * 8;
            atomicAdd(d + 0, s0);
            atomicAdd(d + 1, s1);
            atomicAdd(d + 2, s2);
            atomicAdd(d + 3, s3);
            atomicAdd(d + 4, s4);
        }
    }
#undef PREFETCH_A
#undef ISSUE_B
#undef STORE_A
#undef DO_MMA
}

// ---------------------------------------------------------------------------
// Final combine: per-row quadratic form, write [pred_pos(2048) | pred_neg(2048)]
__global__ void final_kernel(const float* __restrict__ bias, float* __restrict__ out) {
    int warp = threadIdx.x >> 5, lane = threadIdx.x & 31;
    int row = blockIdx.x * 8 + warp;
    if (row >= B_ROWS) return;

    const float* aS = g_acc + (size_t)row * NCOLS;
    const float* aP = g_acc + ((size_t)B_ROWS + row) * NCOLS;
    const float* aN = g_acc + ((size_t)2 * B_ROWS + row) * NCOLS;

    float t5p = 0.f, t6p = 0.f, dgp = 0.f;
    float t5n = 0.f, t6n = 0.f, dgn = 0.f;
#pragma unroll
    for (int f = lane; f < NFEAT; f += 32) {
        float vs = aS[f],         vp = aP[f],         vn = aN[f];
        float ts = aS[NFEAT + f], tp = aP[NFEAT + f], tn = aN[NFEAT + f];
        float vxp = vs + vp, txp = ts + tp;
        float vxn = vs + vn, txn = ts + tn;
        t5p += vxp * vxp; t6p += txp * vxp; dgp += txp * txp;
        t5n += vxn * vxn; t6n += txn * vxn; dgn += txn * txn;
    }
#pragma unroll
    for (int o = 16; o; o >>= 1) {
        t5p += __shfl_down_sync(0xffffffffu, t5p, o);
        t6p += __shfl_down_sync(0xffffffffu, t6p, o);
        dgp += __shfl_down_sync(0xffffffffu, dgp, o);
        t5n += __shfl_down_sync(0xffffffffu, t5n, o);
        t6n += __shfl_down_sync(0xffffffffu, t6n, o);
        dgn += __shfl_down_sync(0xffffffffu, dgn, o);
    }
    if (lane == 0) {
        const float* sS = g_scal + (size_t)(0 * B_ROWS + row) * 8;
        const float* sP = g_scal + (size_t)(1 * B_ROWS + row) * 8;
        const float* sN = g_scal + (size_t)(2 * B_ROWS + row) * 8;

        float zvvp = sS[0] + sP[0], zttp = sS[1] + sP[1], zvtp = sS[2] + sP[2], zsp = sS[4] + sP[4];
        float zvvn = sS[0] + sN[0], zttn = sS[1] + sN[1], zvtn = sS[2] + sN[2], zsn = sS[4] + sN[4];
        float lin_neg = sS[3] + sN[3] + bias[0];

        float qp = 0.5f * (zsp * zvvp + 2.f * zsp * zttp + 2.f * zsp * zvtp
                           - 2.f * t5p - 2.f * t6p) - 0.5f * dgp;
        float qn = 0.5f * (zsn * zvvn + 2.f * zsn * zttn + 2.f * zsn * zvtn
                           - 2.f * t5n - 2.f * t6n) - 0.5f * dgn;

        out[row]          = lin_neg + qp;
        out[B_ROWS + row] = lin_neg + qn;
    }
}

// ---------------------------------------------------------------------------
extern "C" void kernel_launch(void* const* d_in, const int* in_sizes, int n_in,
                              void* d_out, int out_size) {
    const float* u     = (const float*)d_in[0];
    const float* xprev = (const float*)d_in[1];
    const float* xpos  = (const float*)d_in[2];
    const float* xneg  = (const float*)d_in[3];
    const float* V     = (const float*)d_in[4];
    const float* T     = (const float*)d_in[5];
    const float* W     = (const float*)d_in[6];
    const float* bias  = (const float*)d_in[7];
    float* out = (float*)d_out;

    cudaFuncSetAttribute(gemm_kernel, cudaFuncAttributeMaxDynamicSharedMemorySize, SMEM_DYN);

    zero_kernel<<<512, 256>>>();
    gram_kernel<<<(K_TOTAL + 7) / 8, 256>>>(V, T);
    prep_vt<<<dim3(KPAD / 64, 2), 256>>>(V, T);
    gemm_kernel<<<dim3(28, 16, 2), 256, SMEM_DYN>>>(u, xprev, xpos, xneg, W);
    final_kernel<<<B_ROWS / 8, 256>>>(bias, out);
}